// round 3
// baseline (speedup 1.0000x reference)
#include <cuda_runtime.h>

#define NN 50000
#define EE 800000
#define NG 64
#define FD 128
#define QD 768
#define OD 32

// ---------------- scratch (no allocations allowed) ----------------
__device__ float g_dinv[NN];
__device__ float g_hs  [(size_t)NN * FD];
__device__ float g_aggA[(size_t)NN * FD];
__device__ float g_aggB[(size_t)NN * FD];
__device__ float g_q [NG * FD];
__device__ float g_qc[NG * FD];

// ---------------- degree / dinv ----------------
__global__ void k_deg_init() {
    int i = blockIdx.x * blockDim.x + threadIdx.x;
    if (i < NN) g_dinv[i] = 1.0f;   // self-loop
}

__global__ void k_deg_count(const int* __restrict__ dst) {
    int i = blockIdx.x * blockDim.x + threadIdx.x;
    int stride = gridDim.x * blockDim.x;
    for (; i < EE; i += stride)
        atomicAdd(&g_dinv[dst[i]], 1.0f);
}

__global__ void k_dinv() {
    int i = blockIdx.x * blockDim.x + threadIdx.x;
    if (i < NN) g_dinv[i] = rsqrtf(g_dinv[i]);   // deg >= 1 always
}

// ---------------- main GEMM: [M,128] x [128,128] ----------------
// IN_TRANS: a := relu(dinv[row]*a + bias_in[k])  (fused previous conv finalize)
// EPI==0 (conv): v = acc*dinv[row]; write to out0 (hs) and out1 (agg seed = self term)
// EPI==1 (fc1):  v = relu(acc + qc[batch[row]][col]); write out0
template<bool IN_TRANS, int EPI>
__global__ void __launch_bounds__(256)
k_gemm(const float* __restrict__ A, const float* __restrict__ B,
       const float* __restrict__ bias_in,
       float* __restrict__ out0, float* __restrict__ out1,
       const float* __restrict__ qc, const int* __restrict__ batch,
       int M)
{
    __shared__ float As[8][132];   // padded: conflict-free transpose stores
    __shared__ float Bs[8][128];

    const int tid = threadIdx.x;
    const int tx = tid & 15;
    const int ty = tid >> 4;
    const int rowBase = blockIdx.x << 7;

    const int arow = tid >> 1;            // 0..127
    const int acol = (tid & 1) << 2;      // 0 or 4
    const int brow = tid >> 5;            // 0..7
    const int bcol = (tid & 31) << 2;     // 0..124

    float acc[8][8] = {};

    const int ga_row = rowBase + arow;
    const bool arow_ok = ga_row < M;
    float dv = 0.f;
    if (IN_TRANS && arow_ok) dv = g_dinv[ga_row];

    const float* Aptr = A + (size_t)ga_row * FD + acol;
    const float* Bptr = B + brow * FD + bcol;

    for (int k0 = 0; k0 < FD; k0 += 8) {
        float4 av = make_float4(0.f, 0.f, 0.f, 0.f);
        if (arow_ok) av = *(const float4*)(Aptr + k0);
        if (IN_TRANS) {
            float4 bb = *(const float4*)(bias_in + k0 + acol);
            av.x = fmaxf(fmaf(dv, av.x, bb.x), 0.f);
            av.y = fmaxf(fmaf(dv, av.y, bb.y), 0.f);
            av.z = fmaxf(fmaf(dv, av.z, bb.z), 0.f);
            av.w = fmaxf(fmaf(dv, av.w, bb.w), 0.f);
        }
        float4 bv = *(const float4*)(Bptr + (size_t)k0 * FD);

        __syncthreads();
        As[acol + 0][arow] = av.x;
        As[acol + 1][arow] = av.y;
        As[acol + 2][arow] = av.z;
        As[acol + 3][arow] = av.w;
        *(float4*)&Bs[brow][bcol] = bv;
        __syncthreads();

        #pragma unroll
        for (int kk = 0; kk < 8; kk++) {
            float a[8], b[8];
            *(float4*)&a[0] = *(const float4*)&As[kk][ty * 8];
            *(float4*)&a[4] = *(const float4*)&As[kk][ty * 8 + 4];
            *(float4*)&b[0] = *(const float4*)&Bs[kk][tx * 8];
            *(float4*)&b[4] = *(const float4*)&Bs[kk][tx * 8 + 4];
            #pragma unroll
            for (int i = 0; i < 8; i++)
                #pragma unroll
                for (int j = 0; j < 8; j++)
                    acc[i][j] = fmaf(a[i], b[j], acc[i][j]);
        }
    }

    #pragma unroll
    for (int i = 0; i < 8; i++) {
        int r = rowBase + ty * 8 + i;
        if (r >= M) continue;
        float* o0 = out0 + (size_t)r * FD + tx * 8;
        if (EPI == 0) {
            float d = g_dinv[r];
            float4 v0 = make_float4(acc[i][0]*d, acc[i][1]*d, acc[i][2]*d, acc[i][3]*d);
            float4 v1 = make_float4(acc[i][4]*d, acc[i][5]*d, acc[i][6]*d, acc[i][7]*d);
            *(float4*)o0 = v0; *(float4*)(o0 + 4) = v1;
            float* o1 = out1 + (size_t)r * FD + tx * 8;
            *(float4*)o1 = v0; *(float4*)(o1 + 4) = v1;
        } else {
            int g = batch[r];
            const float* qp = qc + g * FD + tx * 8;
            float4 q0 = *(const float4*)qp;
            float4 q1 = *(const float4*)(qp + 4);
            float4 v0 = make_float4(fmaxf(acc[i][0] + q0.x, 0.f),
                                    fmaxf(acc[i][1] + q0.y, 0.f),
                                    fmaxf(acc[i][2] + q0.z, 0.f),
                                    fmaxf(acc[i][3] + q0.w, 0.f));
            float4 v1 = make_float4(fmaxf(acc[i][4] + q1.x, 0.f),
                                    fmaxf(acc[i][5] + q1.y, 0.f),
                                    fmaxf(acc[i][6] + q1.z, 0.f),
                                    fmaxf(acc[i][7] + q1.w, 0.f));
            *(float4*)o0 = v0; *(float4*)(o0 + 4) = v1;
        }
    }
}

// ---------------- edge scatter: agg[dst] += hs[src] ----------------
// one warp per edge; 4 coalesced scalar REDs per lane (lane + 32*j addressing,
// each RED instruction covers one contiguous 128B line)
__global__ void __launch_bounds__(256)
k_scatter(const int* __restrict__ src, const int* __restrict__ dst,
          const float* __restrict__ hs, float* __restrict__ agg)
{
    const int lane = threadIdx.x & 31;
    const int warp = (blockIdx.x * blockDim.x + threadIdx.x) >> 5;
    const int nw = (gridDim.x * blockDim.x) >> 5;
    for (int e = warp; e < EE; e += nw) {
        int s = __ldg(src + e);
        int d = __ldg(dst + e);
        const float* hp = hs + (size_t)s * FD + lane;
        float*       ap = agg + (size_t)d * FD + lane;
        float v0 = hp[0];
        float v1 = hp[32];
        float v2 = hp[64];
        float v3 = hp[96];
        atomicAdd(ap +  0, v0);
        atomicAdd(ap + 32, v1);
        atomicAdd(ap + 64, v2);
        atomicAdd(ap + 96, v3);
    }
}

// ---------------- question head: q = relu(qe @ fc0_w + fc0_b) ----------------
__global__ void k_fc0(const float* __restrict__ qe, const float* __restrict__ w,
                      const float* __restrict__ b)
{
    __shared__ float sq[QD];
    int g = blockIdx.x, t = threadIdx.x;
    for (int k = t; k < QD; k += 128) sq[k] = qe[g * QD + k];
    __syncthreads();
    float acc = b[t];
    for (int k = 0; k < QD; k++) acc = fmaf(sq[k], w[k * FD + t], acc);
    g_q[g * FD + t] = fmaxf(acc, 0.f);
}

// qc[g] = q[g] @ fc1_w[128:256,:] + fc1_b   (per-graph contribution table)
__global__ void k_qc(const float* __restrict__ fc1_w, const float* __restrict__ fc1_b)
{
    __shared__ float sq[FD];
    int g = blockIdx.x, t = threadIdx.x;
    sq[t] = g_q[g * FD + t];
    __syncthreads();
    float acc = fc1_b[t];
    for (int k = 0; k < FD; k++) acc = fmaf(sq[k], fc1_w[(FD + k) * FD + t], acc);
    g_qc[g * FD + t] = acc;
}

// ---------------- fc2: out = h @ fc2_w + fc2_b   [50000,128] -> [50000,32] ----------------
__global__ void __launch_bounds__(256)
k_fc2(const float* __restrict__ h, const float* __restrict__ w,
      const float* __restrict__ b, float* __restrict__ out, int M)
{
    __shared__ float WsT[OD][132];     // transposed weights, padded
    __shared__ float sb[OD];
    __shared__ float srow[8][FD];
    int tid = threadIdx.x;
    for (int i = tid; i < FD * OD; i += 256) {
        int k = i >> 5, n = i & 31;
        WsT[n][k] = w[i];
    }
    if (tid < OD) sb[tid] = b[tid];
    __syncthreads();

    int lane = tid & 31, wrp = tid >> 5;
    int wg = blockIdx.x * 8 + wrp;
    int nw = gridDim.x * 8;
    for (int r = wg; r < M; r += nw) {
        float4 rv = *(const float4*)(h + (size_t)r * FD + lane * 4);
        *(float4*)&srow[wrp][lane * 4] = rv;
        __syncwarp();
        float acc = sb[lane];
        #pragma unroll
        for (int k = 0; k < FD; k += 4) {
            float4 x4 = *(const float4*)&srow[wrp][k];
            float4 w4 = *(const float4*)&WsT[lane][k];
            acc = fmaf(x4.x, w4.x, acc);
            acc = fmaf(x4.y, w4.y, acc);
            acc = fmaf(x4.z, w4.z, acc);
            acc = fmaf(x4.w, w4.w, acc);
        }
        out[(size_t)r * OD + lane] = acc;
        __syncwarp();
    }
}

// ---------------- launcher ----------------
extern "C" void kernel_launch(void* const* d_in, const int* in_sizes, int n_in,
                              void* d_out, int out_size)
{
    const float* x     = (const float*)d_in[0];
    const int*   ei    = (const int*)d_in[1];      // int32 (JAX x64 disabled)
    const int*   batch = (const int*)d_in[2];      // int32
    const float* qe    = (const float*)d_in[3];
    const float* W0    = (const float*)d_in[4];
    const float* b0    = (const float*)d_in[5];
    const float* W1    = (const float*)d_in[6];
    const float* b1    = (const float*)d_in[7];
    const float* W2    = (const float*)d_in[8];
    const float* b2    = (const float*)d_in[9];
    const float* fc0w  = (const float*)d_in[10];
    const float* fc0b  = (const float*)d_in[11];
    const float* fc1w  = (const float*)d_in[12];
    const float* fc1b  = (const float*)d_in[13];
    const float* fc2w  = (const float*)d_in[14];
    const float* fc2b  = (const float*)d_in[15];
    float*       out   = (float*)d_out;

    const int* src = ei;
    const int* dst = ei + EE;

    float *hs, *aggA, *aggB, *qc;
    cudaGetSymbolAddress((void**)&hs,   g_hs);
    cudaGetSymbolAddress((void**)&aggA, g_aggA);
    cudaGetSymbolAddress((void**)&aggB, g_aggB);
    cudaGetSymbolAddress((void**)&qc,   g_qc);

    const int GB = (NN + 127) / 128;      // 391 blocks for GEMMs
    const int SB = 1184;                  // scatter blocks (8/SM)

    // degree -> dinv
    k_deg_init<<<(NN + 255) / 256, 256>>>();
    k_deg_count<<<SB, 256>>>(dst);
    k_dinv<<<(NN + 255) / 256, 256>>>();

    // question head (independent, tiny)
    k_fc0<<<NG, 128>>>(qe, fc0w, fc0b);
    k_qc<<<NG, 128>>>(fc1w, fc1b);

    // conv1: hs = (x@W0)*dinv ; aggA seeded with self term
    k_gemm<false, 0><<<GB, 256>>>(x, W0, nullptr, hs, aggA, nullptr, nullptr, NN);
    k_scatter<<<SB, 256>>>(src, dst, hs, aggA);
    // conv2: input = relu(dinv*aggA + b0)
    k_gemm<true, 0><<<GB, 256>>>(aggA, W1, b0, hs, aggB, nullptr, nullptr, NN);
    k_scatter<<<SB, 256>>>(src, dst, hs, aggB);
    // conv3
    k_gemm<true, 0><<<GB, 256>>>(aggB, W2, b1, hs, aggA, nullptr, nullptr, NN);
    k_scatter<<<SB, 256>>>(src, dst, hs, aggA);

    // fc1 (top half only; q-contrib via table) -> hs reused as fc1 output
    k_gemm<true, 1><<<GB, 256>>>(aggA, fc1w, b2, hs, nullptr, qc, batch, NN);

    // fc2 -> d_out
    k_fc2<<<1024, 256>>>(hs, fc2w, fc2b, out, NN);
}

// round 4
// speedup vs baseline: 1.0724x; 1.0724x over previous
#include <cuda_runtime.h>

#define NN 50000
#define EE 800000
#define NG 64
#define FD 128
#define QD 768
#define OD 32

// ---------------- scratch (no allocations allowed) ----------------
__device__ float g_dinv[NN];
__device__ float g_hs  [(size_t)NN * FD];
__device__ float g_aggA[(size_t)NN * FD];
__device__ float g_aggB[(size_t)NN * FD];
__device__ float g_q [NG * FD];
__device__ float g_qc[NG * FD];
__device__ int   g_cnt[NN];
__device__ int   g_off[NN + 1];
__device__ int   g_cur[NN];
__device__ int   g_csr[EE];

// ---------------- CSR build ----------------
__global__ void k_cnt_init() {
    int i = blockIdx.x * blockDim.x + threadIdx.x;
    if (i < NN) g_cnt[i] = 0;
}

__global__ void k_count(const int* __restrict__ dst) {
    int i = blockIdx.x * blockDim.x + threadIdx.x;
    int stride = gridDim.x * blockDim.x;
    for (; i < EE; i += stride)
        atomicAdd(&g_cnt[dst[i]], 1);
}

// single-block exclusive scan over 50K counts -> g_off, g_cur; also dinv
__global__ void __launch_bounds__(1024) k_scan() {
    __shared__ int ps[1024];
    const int t = threadIdx.x;
    const int CH = (NN + 1023) / 1024;           // 49
    int b = t * CH, e = b + CH; if (e > NN) e = NN;
    int s = 0;
    for (int i = b; i < e; i++) s += g_cnt[i];
    ps[t] = s;
    __syncthreads();
    for (int d = 1; d < 1024; d <<= 1) {
        int v = (t >= d) ? ps[t - d] : 0;
        __syncthreads();
        ps[t] += v;
        __syncthreads();
    }
    int run = (t > 0) ? ps[t - 1] : 0;
    for (int i = b; i < e; i++) {
        g_off[i] = run;
        g_cur[i] = run;
        g_dinv[i] = rsqrtf((float)(g_cnt[i] + 1));   // +1 self-loop
        run += g_cnt[i];
    }
    if (t == 1023) g_off[NN] = run;
}

__global__ void k_place(const int* __restrict__ src, const int* __restrict__ dst) {
    int i = blockIdx.x * blockDim.x + threadIdx.x;
    int stride = gridDim.x * blockDim.x;
    for (; i < EE; i += stride) {
        int d = dst[i];
        int p = atomicAdd(&g_cur[d], 1);
        g_csr[p] = src[i];
    }
}

// ---------------- main GEMM: [M,128] x [128,128] ----------------
// IN_TRANS: a := relu(dinv[row]*a + bias_in[k])  (fused previous conv finalize)
// EPI==0 (conv): v = acc*dinv[row] -> out0 (hs)
// EPI==1 (fc1):  v = relu(acc + qc[batch[row]][col]) -> out0
template<bool IN_TRANS, int EPI>
__global__ void __launch_bounds__(256)
k_gemm(const float* __restrict__ A, const float* __restrict__ B,
       const float* __restrict__ bias_in,
       float* __restrict__ out0,
       const float* __restrict__ qc, const int* __restrict__ batch,
       int M)
{
    __shared__ float As[8][132];
    __shared__ float Bs[8][128];

    const int tid = threadIdx.x;
    const int tx = tid & 15;
    const int ty = tid >> 4;
    const int rowBase = blockIdx.x << 7;

    const int arow = tid >> 1;
    const int acol = (tid & 1) << 2;
    const int brow = tid >> 5;
    const int bcol = (tid & 31) << 2;

    float acc[8][8] = {};

    const int ga_row = rowBase + arow;
    const bool arow_ok = ga_row < M;
    float dv = 0.f;
    if (IN_TRANS && arow_ok) dv = g_dinv[ga_row];

    const float* Aptr = A + (size_t)ga_row * FD + acol;
    const float* Bptr = B + brow * FD + bcol;

    for (int k0 = 0; k0 < FD; k0 += 8) {
        float4 av = make_float4(0.f, 0.f, 0.f, 0.f);
        if (arow_ok) av = *(const float4*)(Aptr + k0);
        if (IN_TRANS) {
            float4 bb = *(const float4*)(bias_in + k0 + acol);
            av.x = fmaxf(fmaf(dv, av.x, bb.x), 0.f);
            av.y = fmaxf(fmaf(dv, av.y, bb.y), 0.f);
            av.z = fmaxf(fmaf(dv, av.z, bb.z), 0.f);
            av.w = fmaxf(fmaf(dv, av.w, bb.w), 0.f);
        }
        float4 bv = *(const float4*)(Bptr + (size_t)k0 * FD);

        __syncthreads();
        As[acol + 0][arow] = av.x;
        As[acol + 1][arow] = av.y;
        As[acol + 2][arow] = av.z;
        As[acol + 3][arow] = av.w;
        *(float4*)&Bs[brow][bcol] = bv;
        __syncthreads();

        #pragma unroll
        for (int kk = 0; kk < 8; kk++) {
            float a[8], b[8];
            *(float4*)&a[0] = *(const float4*)&As[kk][ty * 8];
            *(float4*)&a[4] = *(const float4*)&As[kk][ty * 8 + 4];
            *(float4*)&b[0] = *(const float4*)&Bs[kk][tx * 8];
            *(float4*)&b[4] = *(const float4*)&Bs[kk][tx * 8 + 4];
            #pragma unroll
            for (int i = 0; i < 8; i++)
                #pragma unroll
                for (int j = 0; j < 8; j++)
                    acc[i][j] = fmaf(a[i], b[j], acc[i][j]);
        }
    }

    #pragma unroll
    for (int i = 0; i < 8; i++) {
        int r = rowBase + ty * 8 + i;
        if (r >= M) continue;
        float* o0 = out0 + (size_t)r * FD + tx * 8;
        if (EPI == 0) {
            float d = g_dinv[r];
            float4 v0 = make_float4(acc[i][0]*d, acc[i][1]*d, acc[i][2]*d, acc[i][3]*d);
            float4 v1 = make_float4(acc[i][4]*d, acc[i][5]*d, acc[i][6]*d, acc[i][7]*d);
            *(float4*)o0 = v0; *(float4*)(o0 + 4) = v1;
        } else {
            int g = batch[r];
            const float* qp = qc + g * FD + tx * 8;
            float4 q0 = *(const float4*)qp;
            float4 q1 = *(const float4*)(qp + 4);
            float4 v0 = make_float4(fmaxf(acc[i][0] + q0.x, 0.f),
                                    fmaxf(acc[i][1] + q0.y, 0.f),
                                    fmaxf(acc[i][2] + q0.z, 0.f),
                                    fmaxf(acc[i][3] + q0.w, 0.f));
            float4 v1 = make_float4(fmaxf(acc[i][4] + q1.x, 0.f),
                                    fmaxf(acc[i][5] + q1.y, 0.f),
                                    fmaxf(acc[i][6] + q1.z, 0.f),
                                    fmaxf(acc[i][7] + q1.w, 0.f));
            *(float4*)o0 = v0; *(float4*)(o0 + 4) = v1;
        }
    }
}

// ---------------- CSR gather: agg[n] = hs[n] + sum_{e in in(n)} hs[src(e)] ----------------
// warp per node, float4 per lane (32*16B = 512B row), 4-way unroll for MLP
__global__ void __launch_bounds__(256)
k_gather(const float* __restrict__ hs, float* __restrict__ agg)
{
    const int warp = (blockIdx.x * blockDim.x + threadIdx.x) >> 5;
    if (warp >= NN) return;
    const int lane = threadIdx.x & 31;

    const float4* hp = (const float4*)hs;
    float4 a0 = hp[(size_t)warp * 32 + lane];            // self term
    float4 a1 = make_float4(0.f, 0.f, 0.f, 0.f);
    float4 a2 = make_float4(0.f, 0.f, 0.f, 0.f);
    float4 a3 = make_float4(0.f, 0.f, 0.f, 0.f);

    const int e0 = g_off[warp];
    const int e1 = g_off[warp + 1];
    int i = e0;
    for (; i + 4 <= e1; i += 4) {
        int s0 = g_csr[i], s1 = g_csr[i+1], s2 = g_csr[i+2], s3 = g_csr[i+3];
        float4 v0 = hp[(size_t)s0 * 32 + lane];
        float4 v1 = hp[(size_t)s1 * 32 + lane];
        float4 v2 = hp[(size_t)s2 * 32 + lane];
        float4 v3 = hp[(size_t)s3 * 32 + lane];
        a0.x += v0.x; a0.y += v0.y; a0.z += v0.z; a0.w += v0.w;
        a1.x += v1.x; a1.y += v1.y; a1.z += v1.z; a1.w += v1.w;
        a2.x += v2.x; a2.y += v2.y; a2.z += v2.z; a2.w += v2.w;
        a3.x += v3.x; a3.y += v3.y; a3.z += v3.z; a3.w += v3.w;
    }
    for (; i < e1; i++) {
        int s = g_csr[i];
        float4 v = hp[(size_t)s * 32 + lane];
        a0.x += v.x; a0.y += v.y; a0.z += v.z; a0.w += v.w;
    }
    a0.x += a1.x + a2.x + a3.x;
    a0.y += a1.y + a2.y + a3.y;
    a0.z += a1.z + a2.z + a3.z;
    a0.w += a1.w + a2.w + a3.w;
    ((float4*)agg)[(size_t)warp * 32 + lane] = a0;
}

// ---------------- question head ----------------
__global__ void k_qinit(const float* __restrict__ b) {
    int i = blockIdx.x * blockDim.x + threadIdx.x;
    if (i < NG * FD) g_q[i] = b[i & (FD - 1)];
}

// k-split partial: block (g, c); adds partial dot into g_q
__global__ void __launch_bounds__(128)
k_fc0p(const float* __restrict__ qe, const float* __restrict__ w)
{
    __shared__ float sq[FD];
    const int g = blockIdx.x;
    const int c = blockIdx.y;          // 0..5
    const int t = threadIdx.x;
    const int k0 = c * FD;
    sq[t] = qe[g * QD + k0 + t];
    __syncthreads();
    float acc = 0.f;
    #pragma unroll 8
    for (int k = 0; k < FD; k++)
        acc = fmaf(sq[k], w[(k0 + k) * FD + t], acc);
    atomicAdd(&g_q[g * FD + t], acc);
}

// qc[g] = relu(q[g]) @ fc1_w[128:256,:] + fc1_b
__global__ void k_qc(const float* __restrict__ fc1_w, const float* __restrict__ fc1_b)
{
    __shared__ float sq[FD];
    int g = blockIdx.x, t = threadIdx.x;
    sq[t] = fmaxf(g_q[g * FD + t], 0.f);
    __syncthreads();
    float acc = fc1_b[t];
    for (int k = 0; k < FD; k++) acc = fmaf(sq[k], fc1_w[(FD + k) * FD + t], acc);
    g_qc[g * FD + t] = acc;
}

// ---------------- fc2: out = h @ fc2_w + fc2_b   [50000,128] -> [50000,32] ----------------
__global__ void __launch_bounds__(256)
k_fc2(const float* __restrict__ h, const float* __restrict__ w,
      const float* __restrict__ b, float* __restrict__ out, int M)
{
    __shared__ float WsT[OD][132];
    __shared__ float sb[OD];
    __shared__ float srow[8][FD];
    int tid = threadIdx.x;
    for (int i = tid; i < FD * OD; i += 256) {
        int k = i >> 5, n = i & 31;
        WsT[n][k] = w[i];
    }
    if (tid < OD) sb[tid] = b[tid];
    __syncthreads();

    int lane = tid & 31, wrp = tid >> 5;
    int wg = blockIdx.x * 8 + wrp;
    int nw = gridDim.x * 8;
    for (int r = wg; r < M; r += nw) {
        float4 rv = *(const float4*)(h + (size_t)r * FD + lane * 4);
        *(float4*)&srow[wrp][lane * 4] = rv;
        __syncwarp();
        float acc = sb[lane];
        #pragma unroll
        for (int k = 0; k < FD; k += 4) {
            float4 x4 = *(const float4*)&srow[wrp][k];
            float4 w4 = *(const float4*)&WsT[lane][k];
            acc = fmaf(x4.x, w4.x, acc);
            acc = fmaf(x4.y, w4.y, acc);
            acc = fmaf(x4.z, w4.z, acc);
            acc = fmaf(x4.w, w4.w, acc);
        }
        out[(size_t)r * OD + lane] = acc;
        __syncwarp();
    }
}

// ---------------- launcher ----------------
extern "C" void kernel_launch(void* const* d_in, const int* in_sizes, int n_in,
                              void* d_out, int out_size)
{
    const float* x     = (const float*)d_in[0];
    const int*   ei    = (const int*)d_in[1];
    const int*   batch = (const int*)d_in[2];
    const float* qe    = (const float*)d_in[3];
    const float* W0    = (const float*)d_in[4];
    const float* b0    = (const float*)d_in[5];
    const float* W1    = (const float*)d_in[6];
    const float* b1    = (const float*)d_in[7];
    const float* W2    = (const float*)d_in[8];
    const float* b2    = (const float*)d_in[9];
    const float* fc0w  = (const float*)d_in[10];
    const float* fc0b  = (const float*)d_in[11];
    const float* fc1w  = (const float*)d_in[12];
    const float* fc1b  = (const float*)d_in[13];
    const float* fc2w  = (const float*)d_in[14];
    const float* fc2b  = (const float*)d_in[15];
    float*       out   = (float*)d_out;

    const int* src = ei;
    const int* dst = ei + EE;

    float *hs, *aggA, *aggB, *qc;
    cudaGetSymbolAddress((void**)&hs,   g_hs);
    cudaGetSymbolAddress((void**)&aggA, g_aggA);
    cudaGetSymbolAddress((void**)&aggB, g_aggB);
    cudaGetSymbolAddress((void**)&qc,   g_qc);

    const int GB = (NN + 127) / 128;             // 391 GEMM blocks
    const int EB = 800;                          // edge-loop blocks
    const int NB = (NN * 32 + 255) / 256;        // gather: warp per node

    // CSR build + dinv
    k_cnt_init<<<(NN + 255) / 256, 256>>>();
    k_count<<<EB, 256>>>(dst);
    k_scan<<<1, 1024>>>();
    k_place<<<EB, 256>>>(src, dst);

    // question head
    k_qinit<<<(NG * FD + 255) / 256, 256>>>(fc0b);
    {
        dim3 gg(NG, QD / FD);
        k_fc0p<<<gg, 128>>>(qe, fc0w);
    }
    k_qc<<<NG, 128>>>(fc1w, fc1b);

    // conv1
    k_gemm<false, 0><<<GB, 256>>>(x, W0, nullptr, hs, nullptr, nullptr, NN);
    k_gather<<<NB, 256>>>(hs, aggA);
    // conv2
    k_gemm<true, 0><<<GB, 256>>>(aggA, W1, b0, hs, nullptr, nullptr, NN);
    k_gather<<<NB, 256>>>(hs, aggB);
    // conv3
    k_gemm<true, 0><<<GB, 256>>>(aggB, W2, b1, hs, nullptr, nullptr, NN);
    k_gather<<<NB, 256>>>(hs, aggA);

    // fc1 (q-contrib via table)
    k_gemm<true, 1><<<GB, 256>>>(aggA, fc1w, b2, hs, qc, batch, NN);

    // fc2 -> d_out
    k_fc2<<<1024, 256>>>(hs, fc2w, fc2b, out, NN);
}

// round 9
// speedup vs baseline: 1.2873x; 1.2004x over previous
#include <cuda_runtime.h>
#include <cuda_bf16.h>
#include <cstdint>

#define NN 50000
#define EE 800000
#define NG 64
#define FD 128
#define QD 768
#define OD 32

// ---------------- scratch (no allocations allowed) ----------------
__device__ float g_dinv[NN];
__device__ float g_hs  [(size_t)NN * FD];
__device__ float g_aggA[(size_t)NN * FD];
__device__ float g_aggB[(size_t)NN * FD];
__device__ float g_q [NG * FD];
__device__ float g_qc[NG * FD];
__device__ int   g_cnt[NN];
__device__ int   g_off[NN + 1];
__device__ int   g_cur[NN];
__device__ int   g_csr[EE];
// bf16 weight tiles, [n][k] row-major (col-major B operand): 4 matrices x (hi,lo)
__device__ __nv_bfloat16 g_wBhi[4 * FD * FD];
__device__ __nv_bfloat16 g_wBlo[4 * FD * FD];

__device__ __forceinline__ uint32_t smem_u32(const void* p) {
    uint32_t a;
    asm("{ .reg .u64 t; cvta.to.shared.u64 t, %1; cvt.u32.u64 %0, t; }" : "=r"(a) : "l"(p));
    return a;
}
__device__ __forceinline__ void ldsm_x4(uint32_t* r, uint32_t addr) {
    asm volatile("ldmatrix.sync.aligned.m8n8.x4.shared.b16 {%0,%1,%2,%3}, [%4];"
                 : "=r"(r[0]), "=r"(r[1]), "=r"(r[2]), "=r"(r[3]) : "r"(addr));
}
__device__ __forceinline__ void mma16816(float* c, const uint32_t* a, const uint32_t* b) {
    asm volatile(
        "mma.sync.aligned.m16n8k16.row.col.f32.bf16.bf16.f32 "
        "{%0,%1,%2,%3}, {%4,%5,%6,%7}, {%8,%9}, {%0,%1,%2,%3};"
        : "+f"(c[0]), "+f"(c[1]), "+f"(c[2]), "+f"(c[3])
        : "r"(a[0]), "r"(a[1]), "r"(a[2]), "r"(a[3]), "r"(b[0]), "r"(b[1]));
}

// ---------------- CSR build ----------------
__global__ void k_cnt_init() {
    int i = blockIdx.x * blockDim.x + threadIdx.x;
    if (i < NN) g_cnt[i] = 0;
}
__global__ void k_count(const int* __restrict__ dst) {
    int i = blockIdx.x * blockDim.x + threadIdx.x;
    int stride = gridDim.x * blockDim.x;
    for (; i < EE; i += stride) atomicAdd(&g_cnt[dst[i]], 1);
}
__global__ void __launch_bounds__(1024) k_scan() {
    __shared__ int ps[1024];
    const int t = threadIdx.x;
    const int CH = (NN + 1023) / 1024;
    int b = t * CH, e = b + CH; if (e > NN) e = NN;
    int s = 0;
    for (int i = b; i < e; i++) s += g_cnt[i];
    ps[t] = s;
    __syncthreads();
    for (int d = 1; d < 1024; d <<= 1) {
        int v = (t >= d) ? ps[t - d] : 0;
        __syncthreads();
        ps[t] += v;
        __syncthreads();
    }
    int run = (t > 0) ? ps[t - 1] : 0;
    for (int i = b; i < e; i++) {
        g_off[i] = run;
        g_cur[i] = run;
        g_dinv[i] = rsqrtf((float)(g_cnt[i] + 1));
        run += g_cnt[i];
    }
    if (t == 1023) g_off[NN] = run;
}
__global__ void k_place(const int* __restrict__ src, const int* __restrict__ dst) {
    int i = blockIdx.x * blockDim.x + threadIdx.x;
    int stride = gridDim.x * blockDim.x;
    for (; i < EE; i += stride) {
        int d = dst[i];
        int p = atomicAdd(&g_cur[d], 1);
        g_csr[p] = src[i];
    }
}

// ---------------- weight prep: W[k][n] fp32 -> B[n][k] split bf16 ----------------
__global__ void k_prep(const float* __restrict__ W0, const float* __restrict__ W1,
                       const float* __restrict__ W2, const float* __restrict__ F1)
{
    const float* Ws[4] = {W0, W1, W2, F1};
    int mat = blockIdx.y;
    const float* W = Ws[mat];
    __nv_bfloat16* bh = g_wBhi + mat * FD * FD;
    __nv_bfloat16* bl = g_wBlo + mat * FD * FD;
    for (int idx = blockIdx.x * blockDim.x + threadIdx.x; idx < FD * FD;
         idx += gridDim.x * blockDim.x) {
        int k = idx >> 7, n = idx & 127;
        float v = W[idx];
        __nv_bfloat16 hi = __float2bfloat16_rn(v);
        __nv_bfloat16 lo = __float2bfloat16_rn(v - __bfloat162float(hi));
        bh[n * FD + k] = hi;
        bl[n * FD + k] = lo;
    }
}

// ---------------- tensor-core GEMM: [M,128] x [128,128], split-bf16 3-term ----------------
// IN_TRANS: a := relu(dinv[row]*a + bias_in[k]) on load
// EPI==0: out = acc*dinv[row];  EPI==1: out = relu(acc + qc[batch[row]])
#define SP 136   // padded smem row stride in bf16 elems (272B: odd 16B units -> ldsm conflict-free)
template<bool IN_TRANS, int EPI>
__global__ void __launch_bounds__(256, 1)
k_mma(const float* __restrict__ A, const float* __restrict__ bias_in,
      const __nv_bfloat16* __restrict__ Bhi, const __nv_bfloat16* __restrict__ Blo,
      float* __restrict__ out0,
      const float* __restrict__ qc, const int* __restrict__ batch, int M)
{
    extern __shared__ __align__(16) __nv_bfloat16 sm[];
    __nv_bfloat16* Ah = sm;
    __nv_bfloat16* Al = sm + 128 * SP;
    __nv_bfloat16* Bh = sm + 2 * 128 * SP;
    __nv_bfloat16* Bl = sm + 3 * 128 * SP;

    const int tid = threadIdx.x;
    const int wid = tid >> 5;
    const int lane = tid & 31;
    const int rowBase = blockIdx.x << 7;

    // copy B tiles (16384 bf16 each), 8 bf16 per iteration
    for (int i = tid; i < 2048; i += 256) {
        int n = i >> 4;             // i*8 elems -> n = (i*8)>>7
        int k = (i & 15) << 3;
        uint4 vh = ((const uint4*)Bhi)[i];
        uint4 vl = ((const uint4*)Blo)[i];
        *(uint4*)&Bh[n * SP + k] = vh;
        *(uint4*)&Bl[n * SP + k] = vl;
    }
    // load + transform + split A
    for (int f = tid; f < 4096; f += 256) {
        int row = f >> 5;
        int col = (f & 31) << 2;
        int r = rowBase + row;
        float4 v = make_float4(0.f, 0.f, 0.f, 0.f);
        if (r < M) v = *(const float4*)(A + (size_t)r * FD + col);
        if (IN_TRANS) {
            float dv = (r < M) ? g_dinv[r] : 0.f;
            float4 bb = *(const float4*)(bias_in + col);
            v.x = fmaxf(fmaf(dv, v.x, bb.x), 0.f);
            v.y = fmaxf(fmaf(dv, v.y, bb.y), 0.f);
            v.z = fmaxf(fmaf(dv, v.z, bb.z), 0.f);
            v.w = fmaxf(fmaf(dv, v.w, bb.w), 0.f);
        }
        __nv_bfloat16 hx = __float2bfloat16_rn(v.x);
        __nv_bfloat16 hy = __float2bfloat16_rn(v.y);
        __nv_bfloat16 hz = __float2bfloat16_rn(v.z);
        __nv_bfloat16 hw = __float2bfloat16_rn(v.w);
        __nv_bfloat162 h01, h23, l01, l23;
        h01.x = hx; h01.y = hy; h23.x = hz; h23.y = hw;
        l01.x = __float2bfloat16_rn(v.x - __bfloat162float(hx));
        l01.y = __float2bfloat16_rn(v.y - __bfloat162float(hy));
        l23.x = __float2bfloat16_rn(v.z - __bfloat162float(hz));
        l23.y = __float2bfloat16_rn(v.w - __bfloat162float(hw));
        *(__nv_bfloat162*)&Ah[row * SP + col]     = h01;
        *(__nv_bfloat162*)&Ah[row * SP + col + 2] = h23;
        *(__nv_bfloat162*)&Al[row * SP + col]     = l01;
        *(__nv_bfloat162*)&Al[row * SP + col + 2] = l23;
    }
    __syncthreads();

    const int warp_m = wid & 3;       // 4 m-warps: rows 32*warp_m
    const int warp_n = wid >> 2;      // 2 n-warps: cols 64*warp_n

    float acc[2][8][4];
    #pragma unroll
    for (int i = 0; i < 2; i++)
        #pragma unroll
        for (int j = 0; j < 8; j++)
            #pragma unroll
            for (int q = 0; q < 4; q++) acc[i][j][q] = 0.f;

    const uint32_t sAh = smem_u32(Ah);
    const uint32_t sAl = smem_u32(Al);
    const uint32_t sBh = smem_u32(Bh);
    const uint32_t sBl = smem_u32(Bl);

    // ldmatrix lane addressing
    const int a_row = warp_m * 32 + (lane & 15);       // + i*16
    const int a_kof = (lane >> 4) << 3;                // 0 or 8
    const int b_n   = warp_n * 64 + (lane & 7) + (((lane >> 4) & 1) << 3);  // + pair*16
    const int b_kof = ((lane >> 3) & 1) << 3;          // 0 or 8

    #pragma unroll
    for (int ks = 0; ks < 8; ks++) {
        const int k0 = ks << 4;
        uint32_t ah[2][4], al[2][4];
        #pragma unroll
        for (int i = 0; i < 2; i++) {
            uint32_t off = (uint32_t)((a_row + i * 16) * SP + k0 + a_kof) * 2;
            ldsm_x4(ah[i], sAh + off);
            ldsm_x4(al[i], sAl + off);
        }
        uint32_t bh[4][4], bl[4][4];     // [pair][4 regs: ntile0{k0,k8}, ntile1{k0,k8}]
        #pragma unroll
        for (int p = 0; p < 4; p++) {
            uint32_t off = (uint32_t)((b_n + p * 16) * SP + k0 + b_kof) * 2;
            ldsm_x4(bh[p], sBh + off);
            ldsm_x4(bl[p], sBl + off);
        }
        #pragma unroll
        for (int i = 0; i < 2; i++) {
            #pragma unroll
            for (int j = 0; j < 8; j++) {
                const uint32_t* bfh = &bh[j >> 1][(j & 1) << 1];
                const uint32_t* bfl = &bl[j >> 1][(j & 1) << 1];
                mma16816(acc[i][j], ah[i], bfh);   // hi*hi
                mma16816(acc[i][j], ah[i], bfl);   // hi*lo
                mma16816(acc[i][j], al[i], bfh);   // lo*hi
            }
        }
    }

    // epilogue: lane g=lane>>2 (row within 8), tg=lane&3 (col pair)
    {
        const int g = lane >> 2;
        const int tg = lane & 3;
        #pragma unroll
        for (int i = 0; i < 2; i++) {
            #pragma unroll
            for (int h = 0; h < 2; h++) {
                int r = rowBase + warp_m * 32 + i * 16 + g + h * 8;
                if (r >= M) continue;
                float* o = out0 + (size_t)r * FD;
                if (EPI == 0) {
                    float d = g_dinv[r];
                    #pragma unroll
                    for (int j = 0; j < 8; j++) {
                        int col = warp_n * 64 + j * 8 + tg * 2;
                        float2 v;
                        v.x = acc[i][j][h * 2 + 0] * d;
                        v.y = acc[i][j][h * 2 + 1] * d;
                        *(float2*)(o + col) = v;
                    }
                } else {
                    int gb = batch[r];
                    const float* qp = qc + gb * FD;
                    #pragma unroll
                    for (int j = 0; j < 8; j++) {
                        int col = warp_n * 64 + j * 8 + tg * 2;
                        float2 q = *(const float2*)(qp + col);
                        float2 v;
                        v.x = fmaxf(acc[i][j][h * 2 + 0] + q.x, 0.f);
                        v.y = fmaxf(acc[i][j][h * 2 + 1] + q.y, 0.f);
                        *(float2*)(o + col) = v;
                    }
                }
            }
        }
    }
}

// ---------------- CSR gather: agg[n] = hs[n] + sum_in hs[src] ----------------
__global__ void __launch_bounds__(256)
k_gather(const float* __restrict__ hs, float* __restrict__ agg)
{
    const int warp = (blockIdx.x * blockDim.x + threadIdx.x) >> 5;
    if (warp >= NN) return;
    const int lane = threadIdx.x & 31;

    const float4* hp = (const float4*)hs;
    float4 a0 = hp[(size_t)warp * 32 + lane];
    float4 a1 = make_float4(0.f, 0.f, 0.f, 0.f);
    float4 a2 = make_float4(0.f, 0.f, 0.f, 0.f);
    float4 a3 = make_float4(0.f, 0.f, 0.f, 0.f);

    const int e0 = g_off[warp];
    const int e1 = g_off[warp + 1];
    int i = e0;
    for (; i + 4 <= e1; i += 4) {
        int s0 = g_csr[i], s1 = g_csr[i+1], s2 = g_csr[i+2], s3 = g_csr[i+3];
        float4 v0 = hp[(size_t)s0 * 32 + lane];
        float4 v1 = hp[(size_t)s1 * 32 + lane];
        float4 v2 = hp[(size_t)s2 * 32 + lane];
        float4 v3 = hp[(size_t)s3 * 32 + lane];
        a0.x += v0.x; a0.y += v0.y; a0.z += v0.z; a0.w += v0.w;
        a1.x += v1.x; a1.y += v1.y; a1.z += v1.z; a1.w += v1.w;
        a2.x += v2.x; a2.y += v2.y; a2.z += v2.z; a2.w += v2.w;
        a3.x += v3.x; a3.y += v3.y; a3.z += v3.z; a3.w += v3.w;
    }
    for (; i < e1; i++) {
        int s = g_csr[i];
        float4 v = hp[(size_t)s * 32 + lane];
        a0.x += v.x; a0.y += v.y; a0.z += v.z; a0.w += v.w;
    }
    a0.x += a1.x + a2.x + a3.x;
    a0.y += a1.y + a2.y + a3.y;
    a0.z += a1.z + a2.z + a3.z;
    a0.w += a1.w + a2.w + a3.w;
    ((float4*)agg)[(size_t)warp * 32 + lane] = a0;
}

// ---------------- question head ----------------
__global__ void k_qinit(const float* __restrict__ b) {
    int i = blockIdx.x * blockDim.x + threadIdx.x;
    if (i < NG * FD) g_q[i] = b[i & (FD - 1)];
}
__global__ void __launch_bounds__(128)
k_fc0p(const float* __restrict__ qe, const float* __restrict__ w)
{
    __shared__ float sq[FD];
    const int g = blockIdx.x;
    const int c = blockIdx.y;
    const int t = threadIdx.x;
    const int k0 = c * FD;
    sq[t] = qe[g * QD + k0 + t];
    __syncthreads();
    float acc = 0.f;
    #pragma unroll 8
    for (int k = 0; k < FD; k++)
        acc = fmaf(sq[k], w[(k0 + k) * FD + t], acc);
    atomicAdd(&g_q[g * FD + t], acc);
}
__global__ void k_qc(const float* __restrict__ fc1_w, const float* __restrict__ fc1_b)
{
    __shared__ float sq[FD];
    int g = blockIdx.x, t = threadIdx.x;
    sq[t] = fmaxf(g_q[g * FD + t], 0.f);
    __syncthreads();
    float acc = fc1_b[t];
    for (int k = 0; k < FD; k++) acc = fmaf(sq[k], fc1_w[(FD + k) * FD + t], acc);
    g_qc[g * FD + t] = acc;
}

// ---------------- fc2: [50000,128] -> [50000,32] ----------------
__global__ void __launch_bounds__(256)
k_fc2(const float* __restrict__ h, const float* __restrict__ w,
      const float* __restrict__ b, float* __restrict__ out, int M)
{
    __shared__ float WsT[OD][132];
    __shared__ float sb[OD];
    __shared__ float srow[8][FD];
    int tid = threadIdx.x;
    for (int i = tid; i < FD * OD; i += 256) {
        int k = i >> 5, n = i & 31;
        WsT[n][k] = w[i];
    }
    if (tid < OD) sb[tid] = b[tid];
    __syncthreads();

    int lane = tid & 31, wrp = tid >> 5;
    int wg = blockIdx.x * 8 + wrp;
    int nw = gridDim.x * 8;
    for (int r = wg; r < M; r += nw) {
        float4 rv = *(const float4*)(h + (size_t)r * FD + lane * 4);
        *(float4*)&srow[wrp][lane * 4] = rv;
        __syncwarp();
        float acc = sb[lane];
        #pragma unroll
        for (int k = 0; k < FD; k += 4) {
            float4 x4 = *(const float4*)&srow[wrp][k];
            float4 w4 = *(const float4*)&WsT[lane][k];
            acc = fmaf(x4.x, w4.x, acc);
            acc = fmaf(x4.y, w4.y, acc);
            acc = fmaf(x4.z, w4.z, acc);
            acc = fmaf(x4.w, w4.w, acc);
        }
        out[(size_t)r * OD + lane] = acc;
        __syncwarp();
    }
}

// ---------------- launcher ----------------
extern "C" void kernel_launch(void* const* d_in, const int* in_sizes, int n_in,
                              void* d_out, int out_size)
{
    const float* x     = (const float*)d_in[0];
    const int*   ei    = (const int*)d_in[1];
    const int*   batch = (const int*)d_in[2];
    const float* qe    = (const float*)d_in[3];
    const float* W0    = (const float*)d_in[4];
    const float* b0    = (const float*)d_in[5];
    const float* W1    = (const float*)d_in[6];
    const float* b1    = (const float*)d_in[7];
    const float* W2    = (const float*)d_in[8];
    const float* b2    = (const float*)d_in[9];
    const float* fc0w  = (const float*)d_in[10];
    const float* fc0b  = (const float*)d_in[11];
    const float* fc1w  = (const float*)d_in[12];
    const float* fc1b  = (const float*)d_in[13];
    const float* fc2w  = (const float*)d_in[14];
    const float* fc2b  = (const float*)d_in[15];
    float*       out   = (float*)d_out;

    const int* src = ei;
    const int* dst = ei + EE;

    float *hs, *aggA, *aggB, *qc;
    __nv_bfloat16 *wBhi, *wBlo;
    cudaGetSymbolAddress((void**)&hs,   g_hs);
    cudaGetSymbolAddress((void**)&aggA, g_aggA);
    cudaGetSymbolAddress((void**)&aggB, g_aggB);
    cudaGetSymbolAddress((void**)&qc,   g_qc);
    cudaGetSymbolAddress((void**)&wBhi, g_wBhi);
    cudaGetSymbolAddress((void**)&wBlo, g_wBlo);

    const int SMEM = 4 * 128 * SP * 2;            // 139264 B
    cudaFuncSetAttribute(k_mma<false, 0>, cudaFuncAttributeMaxDynamicSharedMemorySize, SMEM);
    cudaFuncSetAttribute(k_mma<true, 0>,  cudaFuncAttributeMaxDynamicSharedMemorySize, SMEM);
    cudaFuncSetAttribute(k_mma<true, 1>,  cudaFuncAttributeMaxDynamicSharedMemorySize, SMEM);

    const int GB = (NN + 127) / 128;             // 391 tiles
    const int EB = 800;
    const int NB = (NN * 32 + 255) / 256;

    // CSR build + dinv
    k_cnt_init<<<(NN + 255) / 256, 256>>>();
    k_count<<<EB, 256>>>(dst);
    k_scan<<<1, 1024>>>();
    k_place<<<EB, 256>>>(src, dst);

    // weight prep (split + transpose)
    {
        dim3 pg(16, 4);
        k_prep<<<pg, 256>>>(W0, W1, W2, fc1w);
    }

    // question head
    k_qinit<<<(NG * FD + 255) / 256, 256>>>(fc0b);
    {
        dim3 gg(NG, QD / FD);
        k_fc0p<<<gg, 128>>>(qe, fc0w);
    }
    k_qc<<<NG, 128>>>(fc1w, fc1b);

    // conv1
    k_mma<false, 0><<<GB, 256, SMEM>>>(x, nullptr, wBhi + 0 * FD * FD, wBlo + 0 * FD * FD,
                                       hs, nullptr, nullptr, NN);
    k_gather<<<NB, 256>>>(hs, aggA);
    // conv2
    k_mma<true, 0><<<GB, 256, SMEM>>>(aggA, b0, wBhi + 1 * FD * FD, wBlo + 1 * FD * FD,
                                      hs, nullptr, nullptr, NN);
    k_gather<<<NB, 256>>>(hs, aggB);
    // conv3
    k_mma<true, 0><<<GB, 256, SMEM>>>(aggB, b1, wBhi + 2 * FD * FD, wBlo + 2 * FD * FD,
                                      hs, nullptr, nullptr, NN);
    k_gather<<<NB, 256>>>(hs, aggA);

    // fc1 (q-contrib via table)
    k_mma<true, 1><<<GB, 256, SMEM>>>(aggA, b2, wBhi + 3 * FD * FD, wBlo + 3 * FD * FD,
                                      hs, qc, batch, NN);

    // fc2 -> d_out
    k_fc2<<<1024, 256>>>(hs, fc2w, fc2b, out, NN);
}